// round 12
// baseline (speedup 1.0000x reference)
#include <cuda_runtime.h>
#include <math.h>
#include <stdint.h>

#define B_ 4
#define S_ 2048
#define DM 512
#define H_ 8

// ---------------- scratch (device globals; no runtime alloc) ----------------
__device__ uint32_t g_bh[(size_t)8192*256], g_bl[(size_t)8192*256];   // LN out hi/lo (bf16 pairs)
__device__ uint32_t g_qh[(size_t)8192*256], g_ql[(size_t)8192*256];
__device__ uint32_t g_kh[(size_t)8192*256], g_kl[(size_t)8192*256];
__device__ uint32_t g_vh[(size_t)8192*256], g_vl[(size_t)8192*256];
__device__ uint32_t g_wh[4*131072], g_wl[4*131072];                   // 4 pre-split W
__device__ float    g_oh[(size_t)8192*512];                           // attn out (f32)

// ---------------- bf16 helpers ----------------
__device__ __forceinline__ uint32_t pack_bf16(float even, float odd) {
    uint32_t r;
    asm("cvt.rn.bf16x2.f32 %0, %1, %2;" : "=r"(r) : "f"(odd), "f"(even));
    return r;
}
__device__ __forceinline__ void split2(float x0, float x1, uint32_t& hp, uint32_t& lp) {
    hp = pack_bf16(x0, x1);
    float h0 = __uint_as_float(hp << 16);
    float h1 = __uint_as_float(hp & 0xFFFF0000u);
    lp = pack_bf16(x0 - h0, x1 - h1);
}
__device__ __forceinline__ uint32_t prmt(uint32_t a, uint32_t b, uint32_t s) {
    uint32_t d;
    asm("prmt.b32 %0,%1,%2,%3;" : "=r"(d) : "r"(a), "r"(b), "r"(s));
    return d;
}
__device__ __forceinline__ void mma16(float* c, uint4 a, uint32_t b0, uint32_t b1) {
    asm("mma.sync.aligned.m16n8k16.row.col.f32.bf16.bf16.f32 "
        "{%0,%1,%2,%3}, {%4,%5,%6,%7}, {%8,%9}, {%0,%1,%2,%3};"
        : "+f"(c[0]), "+f"(c[1]), "+f"(c[2]), "+f"(c[3])
        : "r"(a.x), "r"(a.y), "r"(a.z), "r"(a.w), "r"(b0), "r"(b1));
}

// ---------------- fragment-order smem layout (g-stride 20: bank-safe) ----------------
#define A_SZ 2560              // 2 kc * 8 mt * (8 g * 20)
#define B_SZ 1280              // 2 kc * 4 nt * 160
#define BUF_SZ (2*A_SZ + 2*B_SZ)   // 7680 u32 = 30KB; x2 buffers = 60KB

__device__ __forceinline__ int ia_(int kc, int mt, int g, int t) {
    return (kc * 8 + mt) * 160 + g * 20 + t * 4;
}
__device__ __forceinline__ int ib_(int kc, int nt, int g, int t) {
    return (kc * 4 + nt) * 160 + g * 20 + t * 4;
}

// ---------------- staging ----------------
__device__ __forceinline__ void loadA_cp(const uint32_t* __restrict__ Hg,
                                         const uint32_t* __restrict__ Lg,
                                         int tid, uint4 rh[2], uint4 rl[2]) {
    #pragma unroll
    for (int i = 0; i < 2; i++) {
        int slot = tid + i * 256;
        int m = slot >> 2, k8 = slot & 3;
        rh[i] = *(const uint4*)&Hg[(size_t)m * 256 + k8 * 4];
        rl[i] = *(const uint4*)&Lg[(size_t)m * 256 + k8 * 4];
    }
}
__device__ __forceinline__ void storeA_cp(const uint4 rh[2], const uint4 rl[2],
                                          int tid, uint32_t* buf) {
    #pragma unroll
    for (int i = 0; i < 2; i++) {
        int slot = tid + i * 256;
        int m = slot >> 2, k8 = slot & 3;
        int kc = k8 >> 1, kh = k8 & 1, mt = m >> 4, g = m & 7, e = ((m >> 3) & 1) + 2 * kh;
        int b0 = ia_(kc, mt, g, 0) + e;
        buf[b0]          = rh[i].x;
        buf[b0 + 4]      = rh[i].y;
        buf[b0 + 8]      = rh[i].z;
        buf[b0 + 12]     = rh[i].w;
        buf[A_SZ + b0]      = rl[i].x;
        buf[A_SZ + b0 + 4]  = rl[i].y;
        buf[A_SZ + b0 + 8]  = rl[i].z;
        buf[A_SZ + b0 + 12] = rl[i].w;
    }
}
__device__ __forceinline__ void loadB_cp(const uint32_t* __restrict__ Hg,
                                         const uint32_t* __restrict__ Lg,
                                         int tid, uint4& rh, uint4& rl) {
    int n = tid >> 2, k8 = tid & 3;
    rh = *(const uint4*)&Hg[(size_t)n * 256 + k8 * 4];
    rl = *(const uint4*)&Lg[(size_t)n * 256 + k8 * 4];
}
__device__ __forceinline__ void storeB_cp(uint4 rh, uint4 rl, int tid, uint32_t* buf) {
    int n = tid >> 2, k8 = tid & 3;
    int kc = k8 >> 1, kh = k8 & 1, nt = n >> 4, g = n & 7, e = ((n >> 3) & 1) * 2 + kh;
    uint32_t* sB = buf + 2 * A_SZ;
    int b0 = ib_(kc, nt, g, 0) + e;
    sB[b0]      = rh.x;  sB[b0 + 4]  = rh.y;  sB[b0 + 8]  = rh.z;  sB[b0 + 12] = rh.w;
    sB[B_SZ + b0]      = rl.x;  sB[B_SZ + b0 + 4]  = rl.y;
    sB[B_SZ + b0 + 8]  = rl.z;  sB[B_SZ + b0 + 12] = rl.w;
}
__device__ __forceinline__ void loadA_sp(const float* __restrict__ Ag, size_t lda,
                                         int tid, float4 rf[4]) {
    #pragma unroll
    for (int i = 0; i < 2; i++) {
        int slot = tid + i * 256;
        int m = slot >> 2, k8 = slot & 3;
        rf[i * 2]     = *(const float4*)&Ag[(size_t)m * lda + k8 * 8];
        rf[i * 2 + 1] = *(const float4*)&Ag[(size_t)m * lda + k8 * 8 + 4];
    }
}
__device__ __forceinline__ void storeA_sp(const float4 rf[4], int tid, uint32_t* buf) {
    #pragma unroll
    for (int i = 0; i < 2; i++) {
        int slot = tid + i * 256;
        int m = slot >> 2, k8 = slot & 3;
        int kc = k8 >> 1, kh = k8 & 1, mt = m >> 4, g = m & 7, e = ((m >> 3) & 1) + 2 * kh;
        uint32_t h0, h1, h2, h3, l0, l1, l2, l3;
        split2(rf[i*2].x,   rf[i*2].y,   h0, l0);
        split2(rf[i*2].z,   rf[i*2].w,   h1, l1);
        split2(rf[i*2+1].x, rf[i*2+1].y, h2, l2);
        split2(rf[i*2+1].z, rf[i*2+1].w, h3, l3);
        int b0 = ia_(kc, mt, g, 0) + e;
        buf[b0] = h0;  buf[b0 + 4] = h1;  buf[b0 + 8] = h2;  buf[b0 + 12] = h3;
        buf[A_SZ + b0] = l0;  buf[A_SZ + b0 + 4] = l1;
        buf[A_SZ + b0 + 8] = l2;  buf[A_SZ + b0 + 12] = l3;
    }
}
__device__ __forceinline__ void loadBT(const uint32_t* __restrict__ Hg,
                                       const uint32_t* __restrict__ Lg,
                                       int tid, uint32_t rh[4], uint32_t rl[4]) {
    int kq = tid >> 5, np = tid & 31;
    int kb = kq * 4;
    #pragma unroll
    for (int r = 0; r < 4; r++) {
        rh[r] = Hg[(size_t)(kb + r) * 256 + np];
        rl[r] = Lg[(size_t)(kb + r) * 256 + np];
    }
}
__device__ __forceinline__ void storeBT(const uint32_t rh[4], const uint32_t rl[4],
                                        int tid, uint32_t* buf) {
    int kq = tid >> 5, np = tid & 31;
    int kc = kq >> 2, kh = (kq >> 1) & 1, t0 = (kq & 1) * 2;
    int nt = np >> 3, g0 = (np * 2) & 7, hn = (np >> 2) & 1;
    int e = hn * 2 + kh;
    uint32_t* sB = buf + 2 * A_SZ;
    int x0 = ib_(kc, nt, g0, t0) + e;
    int x1 = ib_(kc, nt, g0 + 1, t0) + e;
    sB[x0]     = prmt(rh[0], rh[1], 0x5410);
    sB[x0 + 4] = prmt(rh[2], rh[3], 0x5410);
    sB[x1]     = prmt(rh[0], rh[1], 0x7632);
    sB[x1 + 4] = prmt(rh[2], rh[3], 0x7632);
    sB[B_SZ + x0]     = prmt(rl[0], rl[1], 0x5410);
    sB[B_SZ + x0 + 4] = prmt(rl[2], rl[3], 0x5410);
    sB[B_SZ + x1]     = prmt(rl[0], rl[1], 0x7632);
    sB[B_SZ + x1 + 4] = prmt(rl[2], rl[3], 0x7632);
}

// ---------------- compute ----------------
__device__ __forceinline__ void compute_chunk(const uint32_t* buf, int wm, int wn,
                                              int lane, float acc[2][4][4]) {
    const uint32_t* sAh = buf;
    const uint32_t* sAl = buf + A_SZ;
    const uint32_t* sBh = buf + 2 * A_SZ;
    const uint32_t* sBl = buf + 2 * A_SZ + B_SZ;
    int g = lane >> 2, t = lane & 3;
    #pragma unroll
    for (int kc = 0; kc < 2; kc++) {
        uint4 Ah[2], Al[2], Bh[2], Bl[2];
        #pragma unroll
        for (int mtl = 0; mtl < 2; mtl++) {
            int idx = ia_(kc, wm * 2 + mtl, g, t);
            Ah[mtl] = *(const uint4*)&sAh[idx];
            Al[mtl] = *(const uint4*)&sAl[idx];
        }
        #pragma unroll
        for (int p = 0; p < 2; p++) {
            int idx = ib_(kc, wn * 2 + p, g, t);
            Bh[p] = *(const uint4*)&sBh[idx];
            Bl[p] = *(const uint4*)&sBl[idx];
        }
        #pragma unroll
        for (int mtl = 0; mtl < 2; mtl++) {
            #pragma unroll
            for (int p = 0; p < 2; p++) {
                mma16(acc[mtl][p * 2],     Ah[mtl], Bh[p].x, Bh[p].y);
                mma16(acc[mtl][p * 2],     Ah[mtl], Bl[p].x, Bl[p].y);
                mma16(acc[mtl][p * 2],     Al[mtl], Bh[p].x, Bh[p].y);
                mma16(acc[mtl][p * 2 + 1], Ah[mtl], Bh[p].z, Bh[p].w);
                mma16(acc[mtl][p * 2 + 1], Ah[mtl], Bl[p].z, Bl[p].w);
                mma16(acc[mtl][p * 2 + 1], Al[mtl], Bh[p].z, Bh[p].w);
            }
        }
    }
}

// ---------------- epilogues ----------------
__device__ __forceinline__ void store_f32(float* __restrict__ Cb, size_t ldc,
                                          int wm, int wn, int lane,
                                          float acc[2][4][4], float scale) {
    int g = lane >> 2, t = lane & 3;
    #pragma unroll
    for (int mtl = 0; mtl < 2; mtl++) {
        #pragma unroll
        for (int nt = 0; nt < 4; nt++) {
            size_t row = (size_t)(wm * 32 + mtl * 16 + g);
            size_t col = (size_t)(wn * 32 + nt * 8 + t * 2);
            float2 v0 = {acc[mtl][nt][0] * scale, acc[mtl][nt][1] * scale};
            float2 v1 = {acc[mtl][nt][2] * scale, acc[mtl][nt][3] * scale};
            *(float2*)&Cb[row * ldc + col] = v0;
            *(float2*)&Cb[(row + 8) * ldc + col] = v1;
        }
    }
}
__device__ __forceinline__ void store_split(uint32_t* __restrict__ Ch,
                                            uint32_t* __restrict__ Cl,
                                            int wm, int wn, int lane,
                                            float acc[2][4][4]) {
    int g = lane >> 2, t = lane & 3;
    #pragma unroll
    for (int mtl = 0; mtl < 2; mtl++) {
        #pragma unroll
        for (int nt = 0; nt < 4; nt++) {
            size_t row = (size_t)(wm * 32 + mtl * 16 + g);
            int cu = wn * 16 + nt * 4 + t;
            uint32_t hp, lp;
            split2(acc[mtl][nt][0], acc[mtl][nt][1], hp, lp);
            Ch[row * 256 + cu] = hp;  Cl[row * 256 + cu] = lp;
            split2(acc[mtl][nt][2], acc[mtl][nt][3], hp, lp);
            Ch[(row + 8) * 256 + cu] = hp;  Cl[(row + 8) * 256 + cu] = lp;
        }
    }
}

// ---------------- proj GEMM ----------------
template<int EPI>
__global__ __launch_bounds__(256, 3) void proj_mma(const uint32_t* __restrict__ Ah,
                                                   const uint32_t* __restrict__ Al,
                                                   const uint32_t* __restrict__ Bh,
                                                   const uint32_t* __restrict__ Bl,
                                                   float* __restrict__ Cf,
                                                   uint32_t* __restrict__ Ch,
                                                   uint32_t* __restrict__ Cl) {
    extern __shared__ uint32_t sm[];
    uint32_t* buf0 = sm;
    uint32_t* buf1 = sm + BUF_SZ;
    int tid = threadIdx.x, lane = tid & 31, wid = tid >> 5;
    int wm = wid & 3, wn = wid >> 2;
    size_t m0 = (size_t)blockIdx.y * 128, n0 = (size_t)blockIdx.x * 64;
    const uint32_t* Ahb = Ah + m0 * 256;
    const uint32_t* Alb = Al + m0 * 256;
    const uint32_t* Bhb = Bh + n0 * 256;
    const uint32_t* Blb = Bl + n0 * 256;

    uint4 rah[2], ral[2], rbh, rbl;
    float acc[2][4][4] = {};

    loadA_cp(Ahb, Alb, tid, rah, ral);
    loadB_cp(Bhb, Blb, tid, rbh, rbl);
    storeA_cp(rah, ral, tid, buf0);
    storeB_cp(rbh, rbl, tid, buf0);
    __syncthreads();

    const int NC = DM / 32;   // 16
    for (int c = 0; c < NC; c++) {
        uint32_t* cur = (c & 1) ? buf1 : buf0;
        uint32_t* nxt = (c & 1) ? buf0 : buf1;
        if (c + 1 < NC) {
            loadA_cp(Ahb + (c + 1) * 16, Alb + (c + 1) * 16, tid, rah, ral);
            loadB_cp(Bhb + (c + 1) * 16, Blb + (c + 1) * 16, tid, rbh, rbl);
        }
        compute_chunk(cur, wm, wn, lane, acc);
        if (c + 1 < NC) {
            storeA_cp(rah, ral, tid, nxt);
            storeB_cp(rbh, rbl, tid, nxt);
        }
        __syncthreads();
    }
    if (EPI == 0)
        store_f32(Cf + m0 * DM + n0, DM, wm, wn, lane, acc, 1.0f);
    else
        store_split(Ch + m0 * 256 + (n0 >> 1), Cl + m0 * 256 + (n0 >> 1), wm, wn, lane, acc);
}

// ---------------- scores ----------------
__global__ __launch_bounds__(256, 3) void scores_mma(const uint32_t* __restrict__ Qh,
                                                     const uint32_t* __restrict__ Ql,
                                                     const uint32_t* __restrict__ Kh,
                                                     const uint32_t* __restrict__ Kl,
                                                     float* __restrict__ attn) {
    extern __shared__ uint32_t sm[];
    uint32_t* buf0 = sm;
    uint32_t* buf1 = sm + BUF_SZ;
    int tid = threadIdx.x, lane = tid & 31, wid = tid >> 5;
    int wm = wid & 3, wn = wid >> 2;
    int bh = blockIdx.z, b = bh >> 3, h = bh & 7;
    size_t sq0 = (size_t)blockIdx.y * 128;
    const uint32_t* Qhb = Qh + ((size_t)b * S_ + sq0) * 256 + h * 32;
    const uint32_t* Qlb = Ql + ((size_t)b * S_ + sq0) * 256 + h * 32;

    uint4 rah[2], ral[2], rbh, rbl;
    loadA_cp(Qhb, Qlb, tid, rah, ral);
    storeA_cp(rah, ral, tid, buf0);
    loadA_cp(Qhb + 16, Qlb + 16, tid, rah, ral);
    storeA_cp(rah, ral, tid, buf1);

    for (int skt = 0; skt < 4; skt++) {
        size_t sk0 = ((size_t)blockIdx.x * 4 + skt) * 64;
        const uint32_t* Khb = Kh + ((size_t)b * S_ + sk0) * 256 + h * 32;
        const uint32_t* Klb = Kl + ((size_t)b * S_ + sk0) * 256 + h * 32;
        loadB_cp(Khb, Klb, tid, rbh, rbl);
        storeB_cp(rbh, rbl, tid, buf0);
        loadB_cp(Khb + 16, Klb + 16, tid, rbh, rbl);
        storeB_cp(rbh, rbl, tid, buf1);
        __syncthreads();
        float acc[2][4][4] = {};
        compute_chunk(buf0, wm, wn, lane, acc);
        compute_chunk(buf1, wm, wn, lane, acc);
        store_f32(attn + ((size_t)bh * S_ + sq0) * S_ + sk0, S_, wm, wn, lane, acc, 0.125f);
        __syncthreads();
    }
}

// ---------------- av ----------------
__global__ __launch_bounds__(256, 3) void av_mma(const float* __restrict__ attn,
                                                 const uint32_t* __restrict__ Vh,
                                                 const uint32_t* __restrict__ Vl,
                                                 float* __restrict__ oh) {
    extern __shared__ uint32_t sm[];
    uint32_t* buf0 = sm;
    uint32_t* buf1 = sm + BUF_SZ;
    int tid = threadIdx.x, lane = tid & 31, wid = tid >> 5;
    int wm = wid & 3, wn = wid >> 2;
    int bh = blockIdx.y, b = bh >> 3, h = bh & 7;
    size_t sq0 = (size_t)blockIdx.x * 128;
    const float* Pb = attn + ((size_t)bh * S_ + sq0) * S_;
    const uint32_t* Vhb = Vh + (size_t)b * S_ * 256 + h * 32;
    const uint32_t* Vlb = Vl + (size_t)b * S_ * 256 + h * 32;

    float4 rf[4];
    uint32_t rth[4], rtl[4];
    float acc[2][4][4] = {};

    loadA_sp(Pb, S_, tid, rf);
    loadBT(Vhb, Vlb, tid, rth, rtl);
    storeA_sp(rf, tid, buf0);
    storeBT(rth, rtl, tid, buf0);
    __syncthreads();

    const int NC = S_ / 32;   // 64
    for (int c = 0; c < NC; c++) {
        uint32_t* cur = (c & 1) ? buf1 : buf0;
        uint32_t* nxt = (c & 1) ? buf0 : buf1;
        if (c + 1 < NC) {
            loadA_sp(Pb + (c + 1) * 32, S_, tid, rf);
            loadBT(Vhb + (size_t)(c + 1) * 32 * 256, Vlb + (size_t)(c + 1) * 32 * 256,
                   tid, rth, rtl);
        }
        compute_chunk(cur, wm, wn, lane, acc);
        if (c + 1 < NC) {
            storeA_sp(rf, tid, nxt);
            storeBT(rth, rtl, tid, nxt);
        }
        __syncthreads();
    }
    store_f32(oh + ((size_t)b * S_ + sq0) * DM + h * 64, DM, wm, wn, lane, acc, 1.0f);
}

// ---------------- weight pre-split ----------------
__global__ void wconv(const float* __restrict__ W, uint32_t* __restrict__ Hh,
                      uint32_t* __restrict__ Hl) {
    int slot = blockIdx.x * 256 + threadIdx.x;
    float2 w = *(const float2*)&W[(size_t)slot * 2];
    uint32_t hp, lp;
    split2(w.x, w.y, hp, lp);
    Hh[slot] = hp;
    Hl[slot] = lp;
}

// ---------------- LayerNorm (shuffle reductions, 2 barriers) ----------------
__global__ void ln_kernel(const float* __restrict__ x, uint32_t* __restrict__ yh,
                          uint32_t* __restrict__ yl, const float* __restrict__ g,
                          const float* __restrict__ bb) {
    int row = blockIdx.x;
    int t = threadIdx.x, lane = t & 31, wid = t >> 5;
    float2 f = *(const float2*)&x[(size_t)row * DM + 2 * t];
    __shared__ float redm[8], redv[8];
    float s = f.x + f.y;
    #pragma unroll
    for (int o = 16; o; o >>= 1) s += __shfl_xor_sync(0xffffffffu, s, o);
    if (lane == 0) redm[wid] = s;
    __syncthreads();
    float mu = 0.f;
    #pragma unroll
    for (int i = 0; i < 8; i++) mu += redm[i];
    mu *= (1.0f / DM);
    float d0 = f.x - mu, d1 = f.y - mu;
    float vv = d0 * d0 + d1 * d1;
    #pragma unroll
    for (int o = 16; o; o >>= 1) vv += __shfl_xor_sync(0xffffffffu, vv, o);
    if (lane == 0) redv[wid] = vv;
    __syncthreads();
    float var = 0.f;
    #pragma unroll
    for (int i = 0; i < 8; i++) var += redv[i];
    float rstd = rsqrtf(var * (1.0f / DM) + 1e-5f);
    float2 gg = *(const float2*)&g[2 * t];
    float2 bv = *(const float2*)&bb[2 * t];
    float y0 = d0 * rstd * gg.x + bv.x;
    float y1 = d1 * rstd * gg.y + bv.y;
    uint32_t hp, lp;
    split2(y0, y1, hp, lp);
    yh[(size_t)row * 256 + t] = hp;
    yl[(size_t)row * 256 + t] = lp;
}

// ---------------- softmax (shuffle reductions, 2 barriers) ----------------
__global__ __launch_bounds__(256) void softmax_kernel(float* __restrict__ attn) {
    size_t row = blockIdx.x;
    float4* p = (float4*)(attn + row * (size_t)S_);
    int tid = threadIdx.x, lane = tid & 31, wid = tid >> 5;
    float4 v0 = p[tid], v1 = p[tid + 256];
    float m = fmaxf(fmaxf(fmaxf(v0.x, v0.y), fmaxf(v0.z, v0.w)),
                    fmaxf(fmaxf(v1.x, v1.y), fmaxf(v1.z, v1.w)));
    __shared__ float redm[8], reds[8];
    #pragma unroll
    for (int o = 16; o; o >>= 1) m = fmaxf(m, __shfl_xor_sync(0xffffffffu, m, o));
    if (lane == 0) redm[wid] = m;
    __syncthreads();
    m = redm[0];
    #pragma unroll
    for (int i = 1; i < 8; i++) m = fmaxf(m, redm[i]);
    v0.x = __expf(v0.x - m); v0.y = __expf(v0.y - m); v0.z = __expf(v0.z - m); v0.w = __expf(v0.w - m);
    v1.x = __expf(v1.x - m); v1.y = __expf(v1.y - m); v1.z = __expf(v1.z - m); v1.w = __expf(v1.w - m);
    float s = v0.x + v0.y + v0.z + v0.w + v1.x + v1.y + v1.z + v1.w;
    #pragma unroll
    for (int o = 16; o; o >>= 1) s += __shfl_xor_sync(0xffffffffu, s, o);
    if (lane == 0) reds[wid] = s;
    __syncthreads();
    s = 0.f;
    #pragma unroll
    for (int i = 0; i < 8; i++) s += reds[i];
    float inv = 1.0f / s;
    v0.x *= inv; v0.y *= inv; v0.z *= inv; v0.w *= inv;
    v1.x *= inv; v1.y *= inv; v1.z *= inv; v1.w *= inv;
    p[tid] = v0;
    p[tid + 256] = v1;
}

extern "C" void kernel_launch(void* const* d_in, const int* in_sizes, int n_in,
                              void* d_out, int out_size) {
    const float* q    = (const float*)d_in[0];
    const float* k    = (const float*)d_in[1];
    const float* v    = (const float*)d_in[2];
    const float* W_Q  = (const float*)d_in[3];
    const float* W_K  = (const float*)d_in[4];
    const float* W_V  = (const float*)d_in[5];
    const float* W_fc = (const float*)d_in[6];
    const float* ln_g = (const float*)d_in[7];
    const float* ln_b = (const float*)d_in[8];

    float* out  = (float*)d_out;                       // [B,S,512]
    float* attn = out + (size_t)B_ * S_ * DM;          // [B,H,S,S]

    uint32_t *bh, *bl, *qh, *ql, *kh, *kl, *vh, *vl, *wh, *wl;
    float* oh;
    cudaGetSymbolAddress((void**)&bh, g_bh);  cudaGetSymbolAddress((void**)&bl, g_bl);
    cudaGetSymbolAddress((void**)&qh, g_qh);  cudaGetSymbolAddress((void**)&ql, g_ql);
    cudaGetSymbolAddress((void**)&kh, g_kh);  cudaGetSymbolAddress((void**)&kl, g_kl);
    cudaGetSymbolAddress((void**)&vh, g_vh);  cudaGetSymbolAddress((void**)&vl, g_vl);
    cudaGetSymbolAddress((void**)&wh, g_wh);  cudaGetSymbolAddress((void**)&wl, g_wl);
    cudaGetSymbolAddress((void**)&oh, g_oh);

    const int SMEM = 2 * BUF_SZ * 4;                   // 61440 B
    cudaFuncSetAttribute(proj_mma<0>, cudaFuncAttributeMaxDynamicSharedMemorySize, SMEM);
    cudaFuncSetAttribute(proj_mma<1>, cudaFuncAttributeMaxDynamicSharedMemorySize, SMEM);
    cudaFuncSetAttribute(scores_mma,  cudaFuncAttributeMaxDynamicSharedMemorySize, SMEM);
    cudaFuncSetAttribute(av_mma,      cudaFuncAttributeMaxDynamicSharedMemorySize, SMEM);

    const int ROWS = B_ * S_;                          // 8192
    dim3 proj_grid(DM / 64, ROWS / 128);               // (8, 64)

    // pre-split weights
    wconv<<<512, 256>>>(W_Q,  wh,              wl);
    wconv<<<512, 256>>>(W_K,  wh + 131072,     wl + 131072);
    wconv<<<512, 256>>>(W_V,  wh + 2 * 131072, wl + 2 * 131072);
    wconv<<<512, 256>>>(W_fc, wh + 3 * 131072, wl + 3 * 131072);

    // Q path
    ln_kernel<<<ROWS, 256>>>(q, bh, bl, ln_g, ln_b);
    proj_mma<1><<<proj_grid, 256, SMEM>>>(bh, bl, wh, wl, nullptr, qh, ql);
    // K path
    ln_kernel<<<ROWS, 256>>>(k, bh, bl, ln_g, ln_b);
    proj_mma<1><<<proj_grid, 256, SMEM>>>(bh, bl, wh + 131072, wl + 131072, nullptr, kh, kl);
    // V path
    ln_kernel<<<ROWS, 256>>>(v, bh, bl, ln_g, ln_b);
    proj_mma<1><<<proj_grid, 256, SMEM>>>(bh, bl, wh + 2 * 131072, wl + 2 * 131072, nullptr, vh, vl);

    // Attention
    scores_mma<<<dim3(8, 16, 32), 256, SMEM>>>(qh, ql, kh, kl, attn);
    softmax_kernel<<<B_ * H_ * S_, 256>>>(attn);
    av_mma<<<dim3(16, 32), 256, SMEM>>>(attn, vh, vl, oh);

    // Output LN + fc
    ln_kernel<<<ROWS, 256>>>(oh, bh, bl, ln_g, ln_b);
    proj_mma<0><<<proj_grid, 256, SMEM>>>(bh, bl, wh + 3 * 131072, wl + 3 * 131072,
                                          out, nullptr, nullptr);
}

// round 13
// speedup vs baseline: 1.1975x; 1.1975x over previous
#include <cuda_runtime.h>
#include <math.h>
#include <stdint.h>

#define B_ 4
#define S_ 2048
#define DM 512
#define H_ 8

// Scratch (device globals — no runtime allocation allowed)
__device__ float g_buf[(size_t)B_*S_*DM];
__device__ float g_qp [(size_t)B_*S_*DM];
__device__ float g_kp [(size_t)B_*S_*DM];
__device__ float g_vp [(size_t)B_*S_*DM];
__device__ float g_oh [(size_t)B_*S_*DM];

// ---------------- bf16 helpers ----------------
__device__ __forceinline__ uint32_t pack_bf16(float even, float odd) {
    uint32_t r;
    asm("cvt.rn.bf16x2.f32 %0, %1, %2;" : "=r"(r) : "f"(odd), "f"(even));
    return r;
}
__device__ __forceinline__ void split2(float x0, float x1, uint32_t& hp, uint32_t& lp) {
    hp = pack_bf16(x0, x1);
    float h0 = __uint_as_float(hp << 16);
    float h1 = __uint_as_float(hp & 0xFFFF0000u);
    lp = pack_bf16(x0 - h0, x1 - h1);
}
__device__ __forceinline__ void mma16(float* c, uint4 a, uint32_t b0, uint32_t b1) {
    asm("mma.sync.aligned.m16n8k16.row.col.f32.bf16.bf16.f32 "
        "{%0,%1,%2,%3}, {%4,%5,%6,%7}, {%8,%9}, {%0,%1,%2,%3};"
        : "+f"(c[0]), "+f"(c[1]), "+f"(c[2]), "+f"(c[3])
        : "r"(a.x), "r"(a.y), "r"(a.z), "r"(a.w), "r"(b0), "r"(b1));
}

// =====================================================================
// bf16x3 GEMM core (R10 configuration — measured 995us total).
// C[128, 64] = A[128, K] * B^T (B as [n][k] row-major, or V[k][n] when
// BTRANS). 8 warps = 4(m) x 2(n); warp tile 32x32. K chunks of 32
// (2 x k16), fragment-order smem, double-buffered.
// =====================================================================

__device__ __forceinline__ void loadA4(const float* __restrict__ As, size_t lda,
                                       int tid, float4* fa) {
    #pragma unroll
    for (int i = 0; i < 4; i++) {
        int lin = tid + i * 256;
        fa[i] = *(const float4*)&As[(size_t)(lin >> 3) * lda + ((lin & 7) << 2)];
    }
}
__device__ __forceinline__ void storeA4(const float4* fa, int tid,
                                        uint32_t* sAh, uint32_t* sAl) {
    #pragma unroll
    for (int i = 0; i < 4; i++) {
        int lin = tid + i * 256;
        int m = lin >> 3, k4 = (lin & 7) << 2;
        int kc = k4 >> 4, mt = m >> 4, halfm = (m >> 3) & 1, g4 = (m & 7) * 4;
        #pragma unroll
        for (int j = 0; j < 2; j++) {
            int lk = (k4 & 15) + 2 * j;
            int idx = ((kc * 8 + mt) * 32 + g4 + ((lk >> 1) & 3)) * 4
                    + halfm + 2 * ((lk >> 3) & 1);
            uint32_t hp, lp;
            if (j == 0) split2(fa[i].x, fa[i].y, hp, lp);
            else        split2(fa[i].z, fa[i].w, hp, lp);
            sAh[idx] = hp;
            sAl[idx] = lp;
        }
    }
}
__device__ __forceinline__ void loadB2(const float* __restrict__ Bs, size_t ldb,
                                       int tid, float4* fb) {
    #pragma unroll
    for (int i = 0; i < 2; i++) {
        int lin = tid + i * 256;
        fb[i] = *(const float4*)&Bs[(size_t)(lin >> 3) * ldb + ((lin & 7) << 2)];
    }
}
__device__ __forceinline__ void storeB2(const float4* fb, int tid,
                                        uint32_t* sBh, uint32_t* sBl) {
    #pragma unroll
    for (int i = 0; i < 2; i++) {
        int lin = tid + i * 256;
        int n = lin >> 3, k4 = (lin & 7) << 2;
        int kc = k4 >> 4, nt = n >> 4, haln = (n >> 3) & 1, g4 = (n & 7) * 4;
        #pragma unroll
        for (int j = 0; j < 2; j++) {
            int lk = (k4 & 15) + 2 * j;
            int idx = ((kc * 4 + nt) * 32 + g4 + ((lk >> 1) & 3)) * 4
                    + haln * 2 + ((lk >> 3) & 1);
            uint32_t hp, lp;
            if (j == 0) split2(fb[i].x, fb[i].y, hp, lp);
            else        split2(fb[i].z, fb[i].w, hp, lp);
            sBh[idx] = hp;
            sBl[idx] = lp;
        }
    }
}
// V[k][n] transposed staging
__device__ __forceinline__ void loadBT(const float* __restrict__ Bs, size_t ldb,
                                       int tid, float4* fb) {
    int k0 = (tid >> 4) * 2, dv4 = (tid & 15) << 2;
    fb[0] = *(const float4*)&Bs[(size_t)k0 * ldb + dv4];
    fb[1] = *(const float4*)&Bs[(size_t)(k0 + 1) * ldb + dv4];
}
__device__ __forceinline__ void storeBT(const float4* fb, int tid,
                                        uint32_t* sBh, uint32_t* sBl) {
    int kp = tid >> 4, dv4 = (tid & 15) << 2;
    int k0 = kp * 2;
    int kc = k0 >> 4, lk = k0 & 15;
    int t = (lk >> 1) & 3, reg = (lk >> 3) & 1;
    const float* e = (const float*)&fb[0];
    const float* o = (const float*)&fb[1];
    #pragma unroll
    for (int j = 0; j < 4; j++) {
        int n = dv4 + j;
        int idx = ((kc * 4 + (n >> 4)) * 32 + (n & 7) * 4 + t) * 4
                + ((n >> 3) & 1) * 2 + reg;
        uint32_t hp, lp;
        split2(e[j], o[j], hp, lp);
        sBh[idx] = hp;
        sBl[idx] = lp;
    }
}

__device__ __forceinline__ void compute_chunk(const uint32_t* buf, int wm, int wn,
                                              int lane, float acc[2][4][4]) {
    const uint32_t* sAh = buf;
    const uint32_t* sAl = buf + 2048;
    const uint32_t* sBh = buf + 4096;
    const uint32_t* sBl = buf + 5120;
    #pragma unroll
    for (int kc = 0; kc < 2; kc++) {
        uint4 Ah[2], Al[2], Bh[2], Bl[2];
        #pragma unroll
        for (int mtl = 0; mtl < 2; mtl++) {
            int idx = ((kc * 8 + wm * 2 + mtl) * 32 + lane) * 4;
            Ah[mtl] = *(const uint4*)&sAh[idx];
            Al[mtl] = *(const uint4*)&sAl[idx];
        }
        #pragma unroll
        for (int p = 0; p < 2; p++) {
            int idx = ((kc * 4 + wn * 2 + p) * 32 + lane) * 4;
            Bh[p] = *(const uint4*)&sBh[idx];
            Bl[p] = *(const uint4*)&sBl[idx];
        }
        #pragma unroll
        for (int mtl = 0; mtl < 2; mtl++) {
            #pragma unroll
            for (int p = 0; p < 2; p++) {
                mma16(acc[mtl][p * 2],     Ah[mtl], Bh[p].x, Bh[p].y);
                mma16(acc[mtl][p * 2],     Ah[mtl], Bl[p].x, Bl[p].y);
                mma16(acc[mtl][p * 2],     Al[mtl], Bh[p].x, Bh[p].y);
                mma16(acc[mtl][p * 2 + 1], Ah[mtl], Bh[p].z, Bh[p].w);
                mma16(acc[mtl][p * 2 + 1], Ah[mtl], Bl[p].z, Bl[p].w);
                mma16(acc[mtl][p * 2 + 1], Al[mtl], Bh[p].z, Bh[p].w);
            }
        }
    }
}

template<bool BTRANS>
__device__ __forceinline__ void gemm_core(
    const float* __restrict__ Ab, size_t lda,
    const float* __restrict__ Bb, size_t ldb,
    float* __restrict__ Cb, size_t ldc,
    float scale, int nchunk, uint32_t* sm)
{
    int tid = threadIdx.x, lane = tid & 31, wid = tid >> 5;
    int wm = wid & 3, wn = wid >> 2;
    int g = lane >> 2, t = lane & 3;
    uint32_t* buf0 = sm;
    uint32_t* buf1 = sm + 6144;

    float4 fa[4], fb[2];
    float acc[2][4][4] = {};

    loadA4(Ab, lda, tid, fa);
    if (!BTRANS) loadB2(Bb, ldb, tid, fb);
    else         loadBT(Bb, ldb, tid, fb);
    storeA4(fa, tid, buf0, buf0 + 2048);
    if (!BTRANS) storeB2(fb, tid, buf0 + 4096, buf0 + 5120);
    else         storeBT(fb, tid, buf0 + 4096, buf0 + 5120);
    __syncthreads();

    for (int c = 0; c < nchunk; c++) {
        uint32_t* cur = (c & 1) ? buf1 : buf0;
        uint32_t* nxt = (c & 1) ? buf0 : buf1;
        if (c + 1 < nchunk) {
            loadA4(Ab + (c + 1) * 32, lda, tid, fa);
            if (!BTRANS) loadB2(Bb + (c + 1) * 32, ldb, tid, fb);
            else         loadBT(Bb + (size_t)(c + 1) * 32 * ldb, ldb, tid, fb);
        }
        compute_chunk(cur, wm, wn, lane, acc);
        if (c + 1 < nchunk) {
            storeA4(fa, tid, nxt, nxt + 2048);
            if (!BTRANS) storeB2(fb, tid, nxt + 4096, nxt + 5120);
            else         storeBT(fb, tid, nxt + 4096, nxt + 5120);
        }
        __syncthreads();
    }

    #pragma unroll
    for (int mtl = 0; mtl < 2; mtl++) {
        #pragma unroll
        for (int nt = 0; nt < 4; nt++) {
            size_t row = (size_t)(wm * 32 + mtl * 16 + g);
            size_t col = (size_t)(wn * 32 + nt * 8 + t * 2);
            float2 v0 = {acc[mtl][nt][0] * scale, acc[mtl][nt][1] * scale};
            float2 v1 = {acc[mtl][nt][2] * scale, acc[mtl][nt][3] * scale};
            *(float2*)&Cb[row * ldc + col] = v0;
            *(float2*)&Cb[(row + 8) * ldc + col] = v1;
        }
    }
}

// ---------------- kernels ----------------
__global__ __launch_bounds__(256) void proj_mma(const float* __restrict__ A,
                                                const float* __restrict__ W,
                                                float* __restrict__ C) {
    extern __shared__ uint32_t sm[];
    gemm_core<false>(A + (size_t)blockIdx.y * 128 * DM, DM,
                     W + (size_t)blockIdx.x * 64 * DM, DM,
                     C + (size_t)blockIdx.y * 128 * DM + blockIdx.x * 64, DM,
                     1.0f, DM / 32, sm);
}

__global__ __launch_bounds__(256) void scores_mma(const float* __restrict__ qp,
                                                  const float* __restrict__ kp,
                                                  float* __restrict__ attn) {
    extern __shared__ uint32_t sm[];
    int bh = blockIdx.z, b = bh >> 3, h = bh & 7;
    size_t sq0 = (size_t)blockIdx.y * 128, sk0 = (size_t)blockIdx.x * 64;
    gemm_core<false>(qp + ((size_t)b * S_ + sq0) * DM + h * 64, DM,
                     kp + ((size_t)b * S_ + sk0) * DM + h * 64, DM,
                     attn + ((size_t)bh * S_ + sq0) * S_ + sk0, S_,
                     0.125f, 2, sm);
}

__global__ __launch_bounds__(256) void av_mma(const float* __restrict__ attn,
                                              const float* __restrict__ vp,
                                              float* __restrict__ oh) {
    extern __shared__ uint32_t sm[];
    int bh = blockIdx.y, b = bh >> 3, h = bh & 7;
    size_t sq0 = (size_t)blockIdx.x * 128;
    gemm_core<true>(attn + ((size_t)bh * S_ + sq0) * S_, S_,
                    vp + (size_t)b * S_ * DM + h * 64, DM,
                    oh + ((size_t)b * S_ + sq0) * DM + h * 64, DM,
                    1.0f, S_ / 32, sm);
}

// ---------------- LayerNorm (shuffle reductions, 2 barriers) ----------------
__global__ void ln_kernel(const float* __restrict__ x, float* __restrict__ y,
                          const float* __restrict__ g, const float* __restrict__ bb) {
    int row = blockIdx.x;
    int t = threadIdx.x, lane = t & 31, wid = t >> 5;
    float2 f = *(const float2*)&x[(size_t)row * DM + 2 * t];
    __shared__ float redm[8], redv[8];
    float s = f.x + f.y;
    #pragma unroll
    for (int o = 16; o; o >>= 1) s += __shfl_xor_sync(0xffffffffu, s, o);
    if (lane == 0) redm[wid] = s;
    __syncthreads();
    float mu = 0.f;
    #pragma unroll
    for (int i = 0; i < 8; i++) mu += redm[i];
    mu *= (1.0f / DM);
    float d0 = f.x - mu, d1 = f.y - mu;
    float vv = d0 * d0 + d1 * d1;
    #pragma unroll
    for (int o = 16; o; o >>= 1) vv += __shfl_xor_sync(0xffffffffu, vv, o);
    if (lane == 0) redv[wid] = vv;
    __syncthreads();
    float var = 0.f;
    #pragma unroll
    for (int i = 0; i < 8; i++) var += redv[i];
    float rstd = rsqrtf(var * (1.0f / DM) + 1e-5f);
    float2 gg = *(const float2*)&g[2 * t];
    float2 bv = *(const float2*)&bb[2 * t];
    float2 out;
    out.x = d0 * rstd * gg.x + bv.x;
    out.y = d1 * rstd * gg.y + bv.y;
    *(float2*)&y[(size_t)row * DM + 2 * t] = out;
}

// ---------------- softmax (shuffle reductions, 2 barriers) ----------------
__global__ __launch_bounds__(256) void softmax_kernel(float* __restrict__ attn) {
    size_t row = blockIdx.x;
    float4* p = (float4*)(attn + row * (size_t)S_);
    int tid = threadIdx.x, lane = tid & 31, wid = tid >> 5;
    float4 v0 = p[tid], v1 = p[tid + 256];
    float m = fmaxf(fmaxf(fmaxf(v0.x, v0.y), fmaxf(v0.z, v0.w)),
                    fmaxf(fmaxf(v1.x, v1.y), fmaxf(v1.z, v1.w)));
    __shared__ float redm[8], reds[8];
    #pragma unroll
    for (int o = 16; o; o >>= 1) m = fmaxf(m, __shfl_xor_sync(0xffffffffu, m, o));
    if (lane == 0) redm[wid] = m;
    __syncthreads();
    m = redm[0];
    #pragma unroll
    for (int i = 1; i < 8; i++) m = fmaxf(m, redm[i]);
    v0.x = __expf(v0.x - m); v0.y = __expf(v0.y - m); v0.z = __expf(v0.z - m); v0.w = __expf(v0.w - m);
    v1.x = __expf(v1.x - m); v1.y = __expf(v1.y - m); v1.z = __expf(v1.z - m); v1.w = __expf(v1.w - m);
    float s = v0.x + v0.y + v0.z + v0.w + v1.x + v1.y + v1.z + v1.w;
    #pragma unroll
    for (int o = 16; o; o >>= 1) s += __shfl_xor_sync(0xffffffffu, s, o);
    if (lane == 0) reds[wid] = s;
    __syncthreads();
    s = 0.f;
    #pragma unroll
    for (int i = 0; i < 8; i++) s += reds[i];
    float inv = 1.0f / s;
    v0.x *= inv; v0.y *= inv; v0.z *= inv; v0.w *= inv;
    v1.x *= inv; v1.y *= inv; v1.z *= inv; v1.w *= inv;
    p[tid] = v0;
    p[tid + 256] = v1;
}

extern "C" void kernel_launch(void* const* d_in, const int* in_sizes, int n_in,
                              void* d_out, int out_size) {
    const float* q    = (const float*)d_in[0];
    const float* k    = (const float*)d_in[1];
    const float* v    = (const float*)d_in[2];
    const float* W_Q  = (const float*)d_in[3];
    const float* W_K  = (const float*)d_in[4];
    const float* W_V  = (const float*)d_in[5];
    const float* W_fc = (const float*)d_in[6];
    const float* ln_g = (const float*)d_in[7];
    const float* ln_b = (const float*)d_in[8];

    float* out  = (float*)d_out;                       // [B,S,512]
    float* attn = out + (size_t)B_ * S_ * DM;          // [B,H,S,S]

    float *buf, *qp, *kp, *vp, *oh;
    cudaGetSymbolAddress((void**)&buf, g_buf);
    cudaGetSymbolAddress((void**)&qp,  g_qp);
    cudaGetSymbolAddress((void**)&kp,  g_kp);
    cudaGetSymbolAddress((void**)&vp,  g_vp);
    cudaGetSymbolAddress((void**)&oh,  g_oh);

    const int SMEM = 48 * 1024;
    cudaFuncSetAttribute(proj_mma,   cudaFuncAttributeMaxDynamicSharedMemorySize, SMEM);
    cudaFuncSetAttribute(scores_mma, cudaFuncAttributeMaxDynamicSharedMemorySize, SMEM);
    cudaFuncSetAttribute(av_mma,     cudaFuncAttributeMaxDynamicSharedMemorySize, SMEM);

    const int ROWS = B_ * S_;                          // 8192
    dim3 proj_grid(DM / 64, ROWS / 128);               // (8, 64)

    // Q path
    ln_kernel<<<ROWS, 256>>>(q, buf, ln_g, ln_b);
    proj_mma<<<proj_grid, 256, SMEM>>>(buf, W_Q, qp);
    // K path
    ln_kernel<<<ROWS, 256>>>(k, buf, ln_g, ln_b);
    proj_mma<<<proj_grid, 256, SMEM>>>(buf, W_K, kp);
    // V path
    ln_kernel<<<ROWS, 256>>>(v, buf, ln_g, ln_b);
    proj_mma<<<proj_grid, 256, SMEM>>>(buf, W_V, vp);

    // Attention
    scores_mma<<<dim3(S_ / 64, S_ / 128, B_ * H_), 256, SMEM>>>(qp, kp, attn);
    softmax_kernel<<<B_ * H_ * S_, 256>>>(attn);
    av_mma<<<dim3(S_ / 128, B_ * H_), 256, SMEM>>>(attn, vp, oh);

    // Output LN + fc
    ln_kernel<<<ROWS, 256>>>(oh, buf, ln_g, ln_b);
    proj_mma<<<proj_grid, 256, SMEM>>>(buf, W_fc, out);
}

// round 14
// speedup vs baseline: 1.2889x; 1.0764x over previous
#include <cuda_runtime.h>
#include <math.h>
#include <stdint.h>

#define B_ 4
#define S_ 2048
#define DM 512
#define H_ 8

// Scratch (device globals — no runtime allocation allowed)
__device__ float g_buf[(size_t)B_*S_*DM];
__device__ float g_qp [(size_t)B_*S_*DM];
__device__ float g_kp [(size_t)B_*S_*DM];
__device__ float g_vp [(size_t)B_*S_*DM];
__device__ float g_oh [(size_t)B_*S_*DM];

// ---------------- bf16 helpers ----------------
__device__ __forceinline__ uint32_t pack_bf16(float even, float odd) {
    uint32_t r;
    asm("cvt.rn.bf16x2.f32 %0, %1, %2;" : "=r"(r) : "f"(odd), "f"(even));
    return r;
}
__device__ __forceinline__ void split2(float x0, float x1, uint32_t& hp, uint32_t& lp) {
    hp = pack_bf16(x0, x1);
    float h0 = __uint_as_float(hp << 16);
    float h1 = __uint_as_float(hp & 0xFFFF0000u);
    lp = pack_bf16(x0 - h0, x1 - h1);
}
__device__ __forceinline__ void mma16(float* c, uint4 a, uint32_t b0, uint32_t b1) {
    asm("mma.sync.aligned.m16n8k16.row.col.f32.bf16.bf16.f32 "
        "{%0,%1,%2,%3}, {%4,%5,%6,%7}, {%8,%9}, {%0,%1,%2,%3};"
        : "+f"(c[0]), "+f"(c[1]), "+f"(c[2]), "+f"(c[3])
        : "r"(a.x), "r"(a.y), "r"(a.z), "r"(a.w), "r"(b0), "r"(b1));
}

// =====================================================================
// bf16x3 GEMM core (R10/R13 configuration).
// C[128, 64] = A[128, K] * B^T. 8 warps = 4(m) x 2(n); warp tile 32x32.
// K chunks of 32 (2 x k16), fragment-order smem, double-buffered.
// A chunk in smem: hi[2048] lo[2048]; B chunk: hi[1024] lo[1024].
// =====================================================================

__device__ __forceinline__ void loadA4(const float* __restrict__ As, size_t lda,
                                       int tid, float4* fa) {
    #pragma unroll
    for (int i = 0; i < 4; i++) {
        int lin = tid + i * 256;
        fa[i] = *(const float4*)&As[(size_t)(lin >> 3) * lda + ((lin & 7) << 2)];
    }
}
__device__ __forceinline__ void storeA4(const float4* fa, int tid,
                                        uint32_t* sAh, uint32_t* sAl) {
    #pragma unroll
    for (int i = 0; i < 4; i++) {
        int lin = tid + i * 256;
        int m = lin >> 3, k4 = (lin & 7) << 2;
        int kc = k4 >> 4, mt = m >> 4, halfm = (m >> 3) & 1, g4 = (m & 7) * 4;
        #pragma unroll
        for (int j = 0; j < 2; j++) {
            int lk = (k4 & 15) + 2 * j;
            int idx = ((kc * 8 + mt) * 32 + g4 + ((lk >> 1) & 3)) * 4
                    + halfm + 2 * ((lk >> 3) & 1);
            uint32_t hp, lp;
            if (j == 0) split2(fa[i].x, fa[i].y, hp, lp);
            else        split2(fa[i].z, fa[i].w, hp, lp);
            sAh[idx] = hp;
            sAl[idx] = lp;
        }
    }
}
__device__ __forceinline__ void loadB2(const float* __restrict__ Bs, size_t ldb,
                                       int tid, float4* fb) {
    #pragma unroll
    for (int i = 0; i < 2; i++) {
        int lin = tid + i * 256;
        fb[i] = *(const float4*)&Bs[(size_t)(lin >> 3) * ldb + ((lin & 7) << 2)];
    }
}
__device__ __forceinline__ void storeB2(const float4* fb, int tid,
                                        uint32_t* sBh, uint32_t* sBl) {
    #pragma unroll
    for (int i = 0; i < 2; i++) {
        int lin = tid + i * 256;
        int n = lin >> 3, k4 = (lin & 7) << 2;
        int kc = k4 >> 4, nt = n >> 4, haln = (n >> 3) & 1, g4 = (n & 7) * 4;
        #pragma unroll
        for (int j = 0; j < 2; j++) {
            int lk = (k4 & 15) + 2 * j;
            int idx = ((kc * 4 + nt) * 32 + g4 + ((lk >> 1) & 3)) * 4
                    + haln * 2 + ((lk >> 3) & 1);
            uint32_t hp, lp;
            if (j == 0) split2(fb[i].x, fb[i].y, hp, lp);
            else        split2(fb[i].z, fb[i].w, hp, lp);
            sBh[idx] = hp;
            sBl[idx] = lp;
        }
    }
}
// V[k][n] transposed staging
__device__ __forceinline__ void loadBT(const float* __restrict__ Bs, size_t ldb,
                                       int tid, float4* fb) {
    int k0 = (tid >> 4) * 2, dv4 = (tid & 15) << 2;
    fb[0] = *(const float4*)&Bs[(size_t)k0 * ldb + dv4];
    fb[1] = *(const float4*)&Bs[(size_t)(k0 + 1) * ldb + dv4];
}
__device__ __forceinline__ void storeBT(const float4* fb, int tid,
                                        uint32_t* sBh, uint32_t* sBl) {
    int kp = tid >> 4, dv4 = (tid & 15) << 2;
    int k0 = kp * 2;
    int kc = k0 >> 4, lk = k0 & 15;
    int t = (lk >> 1) & 3, reg = (lk >> 3) & 1;
    const float* e = (const float*)&fb[0];
    const float* o = (const float*)&fb[1];
    #pragma unroll
    for (int j = 0; j < 4; j++) {
        int n = dv4 + j;
        int idx = ((kc * 4 + (n >> 4)) * 32 + (n & 7) * 4 + t) * 4
                + ((n >> 3) & 1) * 2 + reg;
        uint32_t hp, lp;
        split2(e[j], o[j], hp, lp);
        sBh[idx] = hp;
        sBl[idx] = lp;
    }
}

// compute one 32-k chunk from separate A (hi@0, lo@2048) and B (hi@0, lo@1024) regions
__device__ __forceinline__ void compute_chunk2(const uint32_t* sA, const uint32_t* sB,
                                               int wm, int wn, int lane,
                                               float acc[2][4][4]) {
    const uint32_t* sAh = sA;
    const uint32_t* sAl = sA + 2048;
    const uint32_t* sBh = sB;
    const uint32_t* sBl = sB + 1024;
    #pragma unroll
    for (int kc = 0; kc < 2; kc++) {
        uint4 Ah[2], Al[2], Bh[2], Bl[2];
        #pragma unroll
        for (int mtl = 0; mtl < 2; mtl++) {
            int idx = ((kc * 8 + wm * 2 + mtl) * 32 + lane) * 4;
            Ah[mtl] = *(const uint4*)&sAh[idx];
            Al[mtl] = *(const uint4*)&sAl[idx];
        }
        #pragma unroll
        for (int p = 0; p < 2; p++) {
            int idx = ((kc * 4 + wn * 2 + p) * 32 + lane) * 4;
            Bh[p] = *(const uint4*)&sBh[idx];
            Bl[p] = *(const uint4*)&sBl[idx];
        }
        #pragma unroll
        for (int mtl = 0; mtl < 2; mtl++) {
            #pragma unroll
            for (int p = 0; p < 2; p++) {
                mma16(acc[mtl][p * 2],     Ah[mtl], Bh[p].x, Bh[p].y);
                mma16(acc[mtl][p * 2],     Ah[mtl], Bl[p].x, Bl[p].y);
                mma16(acc[mtl][p * 2],     Al[mtl], Bh[p].x, Bh[p].y);
                mma16(acc[mtl][p * 2 + 1], Ah[mtl], Bh[p].z, Bh[p].w);
                mma16(acc[mtl][p * 2 + 1], Ah[mtl], Bl[p].z, Bl[p].w);
                mma16(acc[mtl][p * 2 + 1], Al[mtl], Bh[p].z, Bh[p].w);
            }
        }
    }
}
__device__ __forceinline__ void compute_chunk(const uint32_t* buf, int wm, int wn,
                                              int lane, float acc[2][4][4]) {
    compute_chunk2(buf, buf + 4096, wm, wn, lane, acc);
}

__device__ __forceinline__ void store_tile(float* __restrict__ Cb, size_t ldc,
                                           int wm, int wn, int lane,
                                           float acc[2][4][4], float scale) {
    int g = lane >> 2, t = lane & 3;
    #pragma unroll
    for (int mtl = 0; mtl < 2; mtl++) {
        #pragma unroll
        for (int nt = 0; nt < 4; nt++) {
            size_t row = (size_t)(wm * 32 + mtl * 16 + g);
            size_t col = (size_t)(wn * 32 + nt * 8 + t * 2);
            float2 v0 = {acc[mtl][nt][0] * scale, acc[mtl][nt][1] * scale};
            float2 v1 = {acc[mtl][nt][2] * scale, acc[mtl][nt][3] * scale};
            *(float2*)&Cb[row * ldc + col] = v0;
            *(float2*)&Cb[(row + 8) * ldc + col] = v1;
        }
    }
}

template<bool BTRANS>
__device__ __forceinline__ void gemm_core(
    const float* __restrict__ Ab, size_t lda,
    const float* __restrict__ Bb, size_t ldb,
    float* __restrict__ Cb, size_t ldc,
    float scale, int nchunk, uint32_t* sm)
{
    int tid = threadIdx.x, lane = tid & 31, wid = tid >> 5;
    int wm = wid & 3, wn = wid >> 2;
    uint32_t* buf0 = sm;
    uint32_t* buf1 = sm + 6144;

    float4 fa[4], fb[2];
    float acc[2][4][4] = {};

    loadA4(Ab, lda, tid, fa);
    if (!BTRANS) loadB2(Bb, ldb, tid, fb);
    else         loadBT(Bb, ldb, tid, fb);
    storeA4(fa, tid, buf0, buf0 + 2048);
    if (!BTRANS) storeB2(fb, tid, buf0 + 4096, buf0 + 5120);
    else         storeBT(fb, tid, buf0 + 4096, buf0 + 5120);
    __syncthreads();

    for (int c = 0; c < nchunk; c++) {
        uint32_t* cur = (c & 1) ? buf1 : buf0;
        uint32_t* nxt = (c & 1) ? buf0 : buf1;
        if (c + 1 < nchunk) {
            loadA4(Ab + (c + 1) * 32, lda, tid, fa);
            if (!BTRANS) loadB2(Bb + (c + 1) * 32, ldb, tid, fb);
            else         loadBT(Bb + (size_t)(c + 1) * 32 * ldb, ldb, tid, fb);
        }
        compute_chunk(cur, wm, wn, lane, acc);
        if (c + 1 < nchunk) {
            storeA4(fa, tid, nxt, nxt + 2048);
            if (!BTRANS) storeB2(fb, tid, nxt + 4096, nxt + 5120);
            else         storeBT(fb, tid, nxt + 4096, nxt + 5120);
        }
        __syncthreads();
    }
    store_tile(Cb, ldc, wm, wn, lane, acc, scale);
}

// ---------------- kernels ----------------
__global__ __launch_bounds__(256) void proj_mma(const float* __restrict__ A,
                                                const float* __restrict__ W,
                                                float* __restrict__ C) {
    extern __shared__ uint32_t sm[];
    gemm_core<false>(A + (size_t)blockIdx.y * 128 * DM, DM,
                     W + (size_t)blockIdx.x * 64 * DM, DM,
                     C + (size_t)blockIdx.y * 128 * DM + blockIdx.x * 64, DM,
                     1.0f, DM / 32, sm);
}

// scores: Q tile (128 rows, K=64) staged ONCE; 8 K-tiles (64 cols each)
// double-buffered. grid (S/512, S/128, B*H) = (4, 16, 32).
// smem: sQ[8192] (2 chunks x hi/lo) + K bufs 2 x [2 chunks x 2048] = 16384 u32 = 64KB
__global__ __launch_bounds__(256) void scores_mma(const float* __restrict__ qp,
                                                  const float* __restrict__ kp,
                                                  float* __restrict__ attn) {
    extern __shared__ uint32_t sm[];
    uint32_t* sQ = sm;              // chunk0: hi 0..2047, lo 2048..4095; chunk1: +4096
    uint32_t* kb0 = sm + 8192;      // [chunk0 hi/lo 2048][chunk1 hi/lo 2048]
    uint32_t* kb1 = sm + 12288;
    int tid = threadIdx.x, lane = tid & 31, wid = tid >> 5;
    int wm = wid & 3, wn = wid >> 2;
    int bh = blockIdx.z, b = bh >> 3, h = bh & 7;
    size_t sq0 = (size_t)blockIdx.y * 128;
    size_t skg = (size_t)blockIdx.x * 512;
    const float* Qb = qp + ((size_t)b * S_ + sq0) * DM + h * 64;
    const float* Kg = kp + ((size_t)b * S_ + skg) * DM + h * 64;

    float4 fa[4], fb[2][2];
    // stage Q (2 chunks), K tile 0 (2 chunks)
    loadA4(Qb, DM, tid, fa);
    storeA4(fa, tid, sQ, sQ + 2048);
    loadA4(Qb + 32, DM, tid, fa);
    storeA4(fa, tid, sQ + 4096, sQ + 6144);
    loadB2(Kg, DM, tid, fb[0]);
    loadB2(Kg + 32, DM, tid, fb[1]);
    storeB2(fb[0], tid, kb0, kb0 + 1024);
    storeB2(fb[1], tid, kb0 + 2048, kb0 + 3072);
    __syncthreads();

    for (int skt = 0; skt < 8; skt++) {
        uint32_t* cur = (skt & 1) ? kb1 : kb0;
        uint32_t* nxt = (skt & 1) ? kb0 : kb1;
        if (skt + 1 < 8) {
            const float* Kt = Kg + (size_t)(skt + 1) * 64 * DM;
            loadB2(Kt, DM, tid, fb[0]);
            loadB2(Kt + 32, DM, tid, fb[1]);
        }
        float acc[2][4][4] = {};
        compute_chunk2(sQ,        cur,        wm, wn, lane, acc);
        compute_chunk2(sQ + 4096, cur + 2048, wm, wn, lane, acc);
        if (skt + 1 < 8) {
            storeB2(fb[0], tid, nxt, nxt + 1024);
            storeB2(fb[1], tid, nxt + 2048, nxt + 3072);
        }
        __syncthreads();
        store_tile(attn + ((size_t)bh * S_ + sq0) * S_ + skg + skt * 64, S_,
                   wm, wn, lane, acc, 0.125f);
    }
}

__global__ __launch_bounds__(256) void av_mma(const float* __restrict__ attn,
                                              const float* __restrict__ vp,
                                              float* __restrict__ oh) {
    extern __shared__ uint32_t sm[];
    int bh = blockIdx.y, b = bh >> 3, h = bh & 7;
    size_t sq0 = (size_t)blockIdx.x * 128;
    gemm_core<true>(attn + ((size_t)bh * S_ + sq0) * S_, S_,
                    vp + (size_t)b * S_ * DM + h * 64, DM,
                    oh + ((size_t)b * S_ + sq0) * DM + h * 64, DM,
                    1.0f, S_ / 32, sm);
}

// ---------------- LayerNorm (shuffle reductions, 2 barriers) ----------------
__global__ void ln_kernel(const float* __restrict__ x, float* __restrict__ y,
                          const float* __restrict__ g, const float* __restrict__ bb) {
    int row = blockIdx.x;
    int t = threadIdx.x, lane = t & 31, wid = t >> 5;
    float2 f = *(const float2*)&x[(size_t)row * DM + 2 * t];
    __shared__ float redm[8], redv[8];
    float s = f.x + f.y;
    #pragma unroll
    for (int o = 16; o; o >>= 1) s += __shfl_xor_sync(0xffffffffu, s, o);
    if (lane == 0) redm[wid] = s;
    __syncthreads();
    float mu = 0.f;
    #pragma unroll
    for (int i = 0; i < 8; i++) mu += redm[i];
    mu *= (1.0f / DM);
    float d0 = f.x - mu, d1 = f.y - mu;
    float vv = d0 * d0 + d1 * d1;
    #pragma unroll
    for (int o = 16; o; o >>= 1) vv += __shfl_xor_sync(0xffffffffu, vv, o);
    if (lane == 0) redv[wid] = vv;
    __syncthreads();
    float var = 0.f;
    #pragma unroll
    for (int i = 0; i < 8; i++) var += redv[i];
    float rstd = rsqrtf(var * (1.0f / DM) + 1e-5f);
    float2 gg = *(const float2*)&g[2 * t];
    float2 bv = *(const float2*)&bb[2 * t];
    float2 out;
    out.x = d0 * rstd * gg.x + bv.x;
    out.y = d1 * rstd * gg.y + bv.y;
    *(float2*)&y[(size_t)row * DM + 2 * t] = out;
}

// ---------------- softmax (shuffle reductions, 2 barriers) ----------------
__global__ __launch_bounds__(256) void softmax_kernel(float* __restrict__ attn) {
    size_t row = blockIdx.x;
    float4* p = (float4*)(attn + row * (size_t)S_);
    int tid = threadIdx.x, lane = tid & 31, wid = tid >> 5;
    float4 v0 = p[tid], v1 = p[tid + 256];
    float m = fmaxf(fmaxf(fmaxf(v0.x, v0.y), fmaxf(v0.z, v0.w)),
                    fmaxf(fmaxf(v1.x, v1.y), fmaxf(v1.z, v1.w)));
    __shared__ float redm[8], reds[8];
    #pragma unroll
    for (int o = 16; o; o >>= 1) m = fmaxf(m, __shfl_xor_sync(0xffffffffu, m, o));
    if (lane == 0) redm[wid] = m;
    __syncthreads();
    m = redm[0];
    #pragma unroll
    for (int i = 1; i < 8; i++) m = fmaxf(m, redm[i]);
    v0.x = __expf(v0.x - m); v0.y = __expf(v0.y - m); v0.z = __expf(v0.z - m); v0.w = __expf(v0.w - m);
    v1.x = __expf(v1.x - m); v1.y = __expf(v1.y - m); v1.z = __expf(v1.z - m); v1.w = __expf(v1.w - m);
    float s = v0.x + v0.y + v0.z + v0.w + v1.x + v1.y + v1.z + v1.w;
    #pragma unroll
    for (int o = 16; o; o >>= 1) s += __shfl_xor_sync(0xffffffffu, s, o);
    if (lane == 0) reds[wid] = s;
    __syncthreads();
    s = 0.f;
    #pragma unroll
    for (int i = 0; i < 8; i++) s += reds[i];
    float inv = 1.0f / s;
    v0.x *= inv; v0.y *= inv; v0.z *= inv; v0.w *= inv;
    v1.x *= inv; v1.y *= inv; v1.z *= inv; v1.w *= inv;
    p[tid] = v0;
    p[tid + 256] = v1;
}

extern "C" void kernel_launch(void* const* d_in, const int* in_sizes, int n_in,
                              void* d_out, int out_size) {
    const float* q    = (const float*)d_in[0];
    const float* k    = (const float*)d_in[1];
    const float* v    = (const float*)d_in[2];
    const float* W_Q  = (const float*)d_in[3];
    const float* W_K  = (const float*)d_in[4];
    const float* W_V  = (const float*)d_in[5];
    const float* W_fc = (const float*)d_in[6];
    const float* ln_g = (const float*)d_in[7];
    const float* ln_b = (const float*)d_in[8];

    float* out  = (float*)d_out;                       // [B,S,512]
    float* attn = out + (size_t)B_ * S_ * DM;          // [B,H,S,S]

    float *buf, *qp, *kp, *vp, *oh;
    cudaGetSymbolAddress((void**)&buf, g_buf);
    cudaGetSymbolAddress((void**)&qp,  g_qp);
    cudaGetSymbolAddress((void**)&kp,  g_kp);
    cudaGetSymbolAddress((void**)&vp,  g_vp);
    cudaGetSymbolAddress((void**)&oh,  g_oh);

    const int SMEM   = 48 * 1024;
    const int SMEM_S = 64 * 1024;
    cudaFuncSetAttribute(proj_mma,   cudaFuncAttributeMaxDynamicSharedMemorySize, SMEM);
    cudaFuncSetAttribute(scores_mma, cudaFuncAttributeMaxDynamicSharedMemorySize, SMEM_S);
    cudaFuncSetAttribute(av_mma,     cudaFuncAttributeMaxDynamicSharedMemorySize, SMEM);

    const int ROWS = B_ * S_;                          // 8192
    dim3 proj_grid(DM / 64, ROWS / 128);               // (8, 64)

    // Q path
    ln_kernel<<<ROWS, 256>>>(q, buf, ln_g, ln_b);
    proj_mma<<<proj_grid, 256, SMEM>>>(buf, W_Q, qp);
    // K path
    ln_kernel<<<ROWS, 256>>>(k, buf, ln_g, ln_b);
    proj_mma<<<proj_grid, 256, SMEM>>>(buf, W_K, kp);
    // V path
    ln_kernel<<<ROWS, 256>>>(v, buf, ln_g, ln_b);
    proj_mma<<<proj_grid, 256, SMEM>>>(buf, W_V, vp);

    // Attention
    scores_mma<<<dim3(S_ / 512, S_ / 128, B_ * H_), 256, SMEM_S>>>(qp, kp, attn);
    softmax_kernel<<<B_ * H_ * S_, 256>>>(attn);
    av_mma<<<dim3(S_ / 128, B_ * H_), 256, SMEM>>>(attn, vp, oh);

    // Output LN + fc
    ln_kernel<<<ROWS, 256>>>(oh, buf, ln_g, ln_b);
    proj_mma<<<proj_grid, 256, SMEM>>>(buf, W_fc, out);
}

// round 15
// speedup vs baseline: 1.3581x; 1.0537x over previous
#include <cuda_runtime.h>
#include <math.h>
#include <stdint.h>

#define B_ 4
#define S_ 2048
#define DM 512
#define H_ 8

// Scratch (device globals — no runtime allocation allowed)
__device__ float g_buf[(size_t)B_*S_*DM];
__device__ float g_qp [(size_t)B_*S_*DM];
__device__ float g_kp [(size_t)B_*S_*DM];
__device__ float g_vp [(size_t)B_*S_*DM];
__device__ float g_oh [(size_t)B_*S_*DM];

// ---------------- bf16 helpers ----------------
__device__ __forceinline__ uint32_t pack_bf16(float even, float odd) {
    uint32_t r;
    asm("cvt.rn.bf16x2.f32 %0, %1, %2;" : "=r"(r) : "f"(odd), "f"(even));
    return r;
}
__device__ __forceinline__ void split2(float x0, float x1, uint32_t& hp, uint32_t& lp) {
    hp = pack_bf16(x0, x1);
    float h0 = __uint_as_float(hp << 16);
    float h1 = __uint_as_float(hp & 0xFFFF0000u);
    lp = pack_bf16(x0 - h0, x1 - h1);
}
__device__ __forceinline__ void mma16(float* c, uint4 a, uint32_t b0, uint32_t b1) {
    asm("mma.sync.aligned.m16n8k16.row.col.f32.bf16.bf16.f32 "
        "{%0,%1,%2,%3}, {%4,%5,%6,%7}, {%8,%9}, {%0,%1,%2,%3};"
        : "+f"(c[0]), "+f"(c[1]), "+f"(c[2]), "+f"(c[3])
        : "r"(a.x), "r"(a.y), "r"(a.z), "r"(a.w), "r"(b0), "r"(b1));
}
// ---------------- fp16 helpers (av only) ----------------
__device__ __forceinline__ uint32_t pack_f16(float even, float odd) {
    uint32_t r;
    asm("cvt.rn.f16x2.f32 %0, %1, %2;" : "=r"(r) : "f"(odd), "f"(even));
    return r;
}
__device__ __forceinline__ void unpack_f16(uint32_t p, float& e, float& o) {
    asm("{\n\t.reg .b16 lo, hi;\n\tmov.b32 {lo, hi}, %2;\n\t"
        "cvt.f32.f16 %0, lo;\n\tcvt.f32.f16 %1, hi;\n\t}"
        : "=f"(e), "=f"(o) : "r"(p));
}
__device__ __forceinline__ void split2h(float x0, float x1, uint32_t& hp, uint32_t& lp) {
    hp = pack_f16(x0, x1);
    float h0, h1;
    unpack_f16(hp, h0, h1);
    lp = pack_f16(x0 - h0, x1 - h1);
}
__device__ __forceinline__ void mma16h(float* c, uint4 a, uint32_t b0, uint32_t b1) {
    asm("mma.sync.aligned.m16n8k16.row.col.f32.f16.f16.f32 "
        "{%0,%1,%2,%3}, {%4,%5,%6,%7}, {%8,%9}, {%0,%1,%2,%3};"
        : "+f"(c[0]), "+f"(c[1]), "+f"(c[2]), "+f"(c[3])
        : "r"(a.x), "r"(a.y), "r"(a.z), "r"(a.w), "r"(b0), "r"(b1));
}

// =====================================================================
// bf16x3 GEMM core (R13/R14 configuration) — proj & scores unchanged.
// =====================================================================

__device__ __forceinline__ void loadA4(const float* __restrict__ As, size_t lda,
                                       int tid, float4* fa) {
    #pragma unroll
    for (int i = 0; i < 4; i++) {
        int lin = tid + i * 256;
        fa[i] = *(const float4*)&As[(size_t)(lin >> 3) * lda + ((lin & 7) << 2)];
    }
}
__device__ __forceinline__ void storeA4(const float4* fa, int tid,
                                        uint32_t* sAh, uint32_t* sAl) {
    #pragma unroll
    for (int i = 0; i < 4; i++) {
        int lin = tid + i * 256;
        int m = lin >> 3, k4 = (lin & 7) << 2;
        int kc = k4 >> 4, mt = m >> 4, halfm = (m >> 3) & 1, g4 = (m & 7) * 4;
        #pragma unroll
        for (int j = 0; j < 2; j++) {
            int lk = (k4 & 15) + 2 * j;
            int idx = ((kc * 8 + mt) * 32 + g4 + ((lk >> 1) & 3)) * 4
                    + halfm + 2 * ((lk >> 3) & 1);
            uint32_t hp, lp;
            if (j == 0) split2(fa[i].x, fa[i].y, hp, lp);
            else        split2(fa[i].z, fa[i].w, hp, lp);
            sAh[idx] = hp;
            sAl[idx] = lp;
        }
    }
}
// A staging, fp16 hi-only (av P tile)
__device__ __forceinline__ void storeA_h(const float4* fa, int tid, uint32_t* sAh) {
    #pragma unroll
    for (int i = 0; i < 4; i++) {
        int lin = tid + i * 256;
        int m = lin >> 3, k4 = (lin & 7) << 2;
        int kc = k4 >> 4, mt = m >> 4, halfm = (m >> 3) & 1, g4 = (m & 7) * 4;
        #pragma unroll
        for (int j = 0; j < 2; j++) {
            int lk = (k4 & 15) + 2 * j;
            int idx = ((kc * 8 + mt) * 32 + g4 + ((lk >> 1) & 3)) * 4
                    + halfm + 2 * ((lk >> 3) & 1);
            sAh[idx] = (j == 0) ? pack_f16(fa[i].x, fa[i].y)
                                : pack_f16(fa[i].z, fa[i].w);
        }
    }
}
__device__ __forceinline__ void loadB2(const float* __restrict__ Bs, size_t ldb,
                                       int tid, float4* fb) {
    #pragma unroll
    for (int i = 0; i < 2; i++) {
        int lin = tid + i * 256;
        fb[i] = *(const float4*)&Bs[(size_t)(lin >> 3) * ldb + ((lin & 7) << 2)];
    }
}
__device__ __forceinline__ void storeB2(const float4* fb, int tid,
                                        uint32_t* sBh, uint32_t* sBl) {
    #pragma unroll
    for (int i = 0; i < 2; i++) {
        int lin = tid + i * 256;
        int n = lin >> 3, k4 = (lin & 7) << 2;
        int kc = k4 >> 4, nt = n >> 4, haln = (n >> 3) & 1, g4 = (n & 7) * 4;
        #pragma unroll
        for (int j = 0; j < 2; j++) {
            int lk = (k4 & 15) + 2 * j;
            int idx = ((kc * 4 + nt) * 32 + g4 + ((lk >> 1) & 3)) * 4
                    + haln * 2 + ((lk >> 3) & 1);
            uint32_t hp, lp;
            if (j == 0) split2(fb[i].x, fb[i].y, hp, lp);
            else        split2(fb[i].z, fb[i].w, hp, lp);
            sBh[idx] = hp;
            sBl[idx] = lp;
        }
    }
}
// V[k][n] transposed staging (fp16 hi/lo)
__device__ __forceinline__ void loadBT(const float* __restrict__ Bs, size_t ldb,
                                       int tid, float4* fb) {
    int k0 = (tid >> 4) * 2, dv4 = (tid & 15) << 2;
    fb[0] = *(const float4*)&Bs[(size_t)k0 * ldb + dv4];
    fb[1] = *(const float4*)&Bs[(size_t)(k0 + 1) * ldb + dv4];
}
__device__ __forceinline__ void storeBT_h(const float4* fb, int tid,
                                          uint32_t* sBh, uint32_t* sBl) {
    int kp = tid >> 4, dv4 = (tid & 15) << 2;
    int k0 = kp * 2;
    int kc = k0 >> 4, lk = k0 & 15;
    int t = (lk >> 1) & 3, reg = (lk >> 3) & 1;
    const float* e = (const float*)&fb[0];
    const float* o = (const float*)&fb[1];
    #pragma unroll
    for (int j = 0; j < 4; j++) {
        int n = dv4 + j;
        int idx = ((kc * 4 + (n >> 4)) * 32 + (n & 7) * 4 + t) * 4
                + ((n >> 3) & 1) * 2 + reg;
        uint32_t hp, lp;
        split2h(e[j], o[j], hp, lp);
        sBh[idx] = hp;
        sBl[idx] = lp;
    }
}

// compute one 32-k chunk, bf16x3 (A: hi@0/lo@2048; B: hi@0/lo@1024)
__device__ __forceinline__ void compute_chunk2(const uint32_t* sA, const uint32_t* sB,
                                               int wm, int wn, int lane,
                                               float acc[2][4][4]) {
    const uint32_t* sAh = sA;
    const uint32_t* sAl = sA + 2048;
    const uint32_t* sBh = sB;
    const uint32_t* sBl = sB + 1024;
    #pragma unroll
    for (int kc = 0; kc < 2; kc++) {
        uint4 Ah[2], Al[2], Bh[2], Bl[2];
        #pragma unroll
        for (int mtl = 0; mtl < 2; mtl++) {
            int idx = ((kc * 8 + wm * 2 + mtl) * 32 + lane) * 4;
            Ah[mtl] = *(const uint4*)&sAh[idx];
            Al[mtl] = *(const uint4*)&sAl[idx];
        }
        #pragma unroll
        for (int p = 0; p < 2; p++) {
            int idx = ((kc * 4 + wn * 2 + p) * 32 + lane) * 4;
            Bh[p] = *(const uint4*)&sBh[idx];
            Bl[p] = *(const uint4*)&sBl[idx];
        }
        #pragma unroll
        for (int mtl = 0; mtl < 2; mtl++) {
            #pragma unroll
            for (int p = 0; p < 2; p++) {
                mma16(acc[mtl][p * 2],     Ah[mtl], Bh[p].x, Bh[p].y);
                mma16(acc[mtl][p * 2],     Ah[mtl], Bl[p].x, Bl[p].y);
                mma16(acc[mtl][p * 2],     Al[mtl], Bh[p].x, Bh[p].y);
                mma16(acc[mtl][p * 2 + 1], Ah[mtl], Bh[p].z, Bh[p].w);
                mma16(acc[mtl][p * 2 + 1], Ah[mtl], Bl[p].z, Bl[p].w);
                mma16(acc[mtl][p * 2 + 1], Al[mtl], Bh[p].z, Bh[p].w);
            }
        }
    }
}
__device__ __forceinline__ void compute_chunk(const uint32_t* buf, int wm, int wn,
                                              int lane, float acc[2][4][4]) {
    compute_chunk2(buf, buf + 4096, wm, wn, lane, acc);
}
// fp16 av chunk: A hi-only @0 (2048); B: Vh@0, Vl@1024
__device__ __forceinline__ void compute_chunk_av(const uint32_t* sA, const uint32_t* sB,
                                                 int wm, int wn, int lane,
                                                 float acc[2][4][4]) {
    const uint32_t* sVh = sB;
    const uint32_t* sVl = sB + 1024;
    #pragma unroll
    for (int kc = 0; kc < 2; kc++) {
        uint4 Ah[2], Bh[2], Bl[2];
        #pragma unroll
        for (int mtl = 0; mtl < 2; mtl++) {
            int idx = ((kc * 8 + wm * 2 + mtl) * 32 + lane) * 4;
            Ah[mtl] = *(const uint4*)&sA[idx];
        }
        #pragma unroll
        for (int p = 0; p < 2; p++) {
            int idx = ((kc * 4 + wn * 2 + p) * 32 + lane) * 4;
            Bh[p] = *(const uint4*)&sVh[idx];
            Bl[p] = *(const uint4*)&sVl[idx];
        }
        #pragma unroll
        for (int mtl = 0; mtl < 2; mtl++) {
            #pragma unroll
            for (int p = 0; p < 2; p++) {
                mma16h(acc[mtl][p * 2],     Ah[mtl], Bh[p].x, Bh[p].y);
                mma16h(acc[mtl][p * 2],     Ah[mtl], Bl[p].x, Bl[p].y);
                mma16h(acc[mtl][p * 2 + 1], Ah[mtl], Bh[p].z, Bh[p].w);
                mma16h(acc[mtl][p * 2 + 1], Ah[mtl], Bl[p].z, Bl[p].w);
            }
        }
    }
}

__device__ __forceinline__ void store_tile(float* __restrict__ Cb, size_t ldc,
                                           int wm, int wn, int lane,
                                           float acc[2][4][4], float scale) {
    int g = lane >> 2, t = lane & 3;
    #pragma unroll
    for (int mtl = 0; mtl < 2; mtl++) {
        #pragma unroll
        for (int nt = 0; nt < 4; nt++) {
            size_t row = (size_t)(wm * 32 + mtl * 16 + g);
            size_t col = (size_t)(wn * 32 + nt * 8 + t * 2);
            float2 v0 = {acc[mtl][nt][0] * scale, acc[mtl][nt][1] * scale};
            float2 v1 = {acc[mtl][nt][2] * scale, acc[mtl][nt][3] * scale};
            *(float2*)&Cb[row * ldc + col] = v0;
            *(float2*)&Cb[(row + 8) * ldc + col] = v1;
        }
    }
}

__device__ __forceinline__ void gemm_core_nn(
    const float* __restrict__ Ab, size_t lda,
    const float* __restrict__ Bb, size_t ldb,
    float* __restrict__ Cb, size_t ldc,
    float scale, int nchunk, uint32_t* sm)
{
    int tid = threadIdx.x, lane = tid & 31, wid = tid >> 5;
    int wm = wid & 3, wn = wid >> 2;
    uint32_t* buf0 = sm;
    uint32_t* buf1 = sm + 6144;

    float4 fa[4], fb[2];
    float acc[2][4][4] = {};

    loadA4(Ab, lda, tid, fa);
    loadB2(Bb, ldb, tid, fb);
    storeA4(fa, tid, buf0, buf0 + 2048);
    storeB2(fb, tid, buf0 + 4096, buf0 + 5120);
    __syncthreads();

    for (int c = 0; c < nchunk; c++) {
        uint32_t* cur = (c & 1) ? buf1 : buf0;
        uint32_t* nxt = (c & 1) ? buf0 : buf1;
        if (c + 1 < nchunk) {
            loadA4(Ab + (c + 1) * 32, lda, tid, fa);
            loadB2(Bb + (c + 1) * 32, ldb, tid, fb);
        }
        compute_chunk(cur, wm, wn, lane, acc);
        if (c + 1 < nchunk) {
            storeA4(fa, tid, nxt, nxt + 2048);
            storeB2(fb, tid, nxt + 4096, nxt + 5120);
        }
        __syncthreads();
    }
    store_tile(Cb, ldc, wm, wn, lane, acc, scale);
}

// ---------------- kernels ----------------
__global__ __launch_bounds__(256) void proj_mma(const float* __restrict__ A,
                                                const float* __restrict__ W,
                                                float* __restrict__ C) {
    extern __shared__ uint32_t sm[];
    gemm_core_nn(A + (size_t)blockIdx.y * 128 * DM, DM,
                 W + (size_t)blockIdx.x * 64 * DM, DM,
                 C + (size_t)blockIdx.y * 128 * DM + blockIdx.x * 64, DM,
                 1.0f, DM / 32, sm);
}

// scores: Q staged once per CTA, 8 K-tiles double-buffered (R14, unchanged)
__global__ __launch_bounds__(256) void scores_mma(const float* __restrict__ qp,
                                                  const float* __restrict__ kp,
                                                  float* __restrict__ attn) {
    extern __shared__ uint32_t sm[];
    uint32_t* sQ = sm;
    uint32_t* kb0 = sm + 8192;
    uint32_t* kb1 = sm + 12288;
    int tid = threadIdx.x, lane = tid & 31, wid = tid >> 5;
    int wm = wid & 3, wn = wid >> 2;
    int bh = blockIdx.z, b = bh >> 3, h = bh & 7;
    size_t sq0 = (size_t)blockIdx.y * 128;
    size_t skg = (size_t)blockIdx.x * 512;
    const float* Qb = qp + ((size_t)b * S_ + sq0) * DM + h * 64;
    const float* Kg = kp + ((size_t)b * S_ + skg) * DM + h * 64;

    float4 fa[4], fb[2][2];
    loadA4(Qb, DM, tid, fa);
    storeA4(fa, tid, sQ, sQ + 2048);
    loadA4(Qb + 32, DM, tid, fa);
    storeA4(fa, tid, sQ + 4096, sQ + 6144);
    loadB2(Kg, DM, tid, fb[0]);
    loadB2(Kg + 32, DM, tid, fb[1]);
    storeB2(fb[0], tid, kb0, kb0 + 1024);
    storeB2(fb[1], tid, kb0 + 2048, kb0 + 3072);
    __syncthreads();

    for (int skt = 0; skt < 8; skt++) {
        uint32_t* cur = (skt & 1) ? kb1 : kb0;
        uint32_t* nxt = (skt & 1) ? kb0 : kb1;
        if (skt + 1 < 8) {
            const float* Kt = Kg + (size_t)(skt + 1) * 64 * DM;
            loadB2(Kt, DM, tid, fb[0]);
            loadB2(Kt + 32, DM, tid, fb[1]);
        }
        float acc[2][4][4] = {};
        compute_chunk2(sQ,        cur,        wm, wn, lane, acc);
        compute_chunk2(sQ + 4096, cur + 2048, wm, wn, lane, acc);
        if (skt + 1 < 8) {
            storeB2(fb[0], tid, nxt, nxt + 1024);
            storeB2(fb[1], tid, nxt + 2048, nxt + 3072);
        }
        __syncthreads();
        store_tile(attn + ((size_t)bh * S_ + sq0) * S_ + skg + skt * 64, S_,
                   wm, wn, lane, acc, 0.125f);
    }
}

// av: fp16 P (single) x fp16 V (hi/lo). Buffers: [P 2048][Vh 1024][Vl 1024] x2 = 32KB.
__global__ __launch_bounds__(256) void av_mma(const float* __restrict__ attn,
                                              const float* __restrict__ vp,
                                              float* __restrict__ oh) {
    extern __shared__ uint32_t sm[];
    uint32_t* buf0 = sm;
    uint32_t* buf1 = sm + 4096;
    int tid = threadIdx.x, lane = tid & 31, wid = tid >> 5;
    int wm = wid & 3, wn = wid >> 2;
    int bh = blockIdx.y, b = bh >> 3, h = bh & 7;
    size_t sq0 = (size_t)blockIdx.x * 128;
    const float* Pb = attn + ((size_t)bh * S_ + sq0) * S_;
    const float* Vb = vp + (size_t)b * S_ * DM + h * 64;

    float4 fa[4], fb[2];
    float acc[2][4][4] = {};

    loadA4(Pb, S_, tid, fa);
    loadBT(Vb, DM, tid, fb);
    storeA_h(fa, tid, buf0);
    storeBT_h(fb, tid, buf0 + 2048, buf0 + 3072);
    __syncthreads();

    const int NC = S_ / 32;   // 64
    for (int c = 0; c < NC; c++) {
        uint32_t* cur = (c & 1) ? buf1 : buf0;
        uint32_t* nxt = (c & 1) ? buf0 : buf1;
        if (c + 1 < NC) {
            loadA4(Pb + (c + 1) * 32, S_, tid, fa);
            loadBT(Vb + (size_t)(c + 1) * 32 * DM, DM, tid, fb);
        }
        compute_chunk_av(cur, cur + 2048, wm, wn, lane, acc);
        if (c + 1 < NC) {
            storeA_h(fa, tid, nxt);
            storeBT_h(fb, tid, nxt + 2048, nxt + 3072);
        }
        __syncthreads();
    }
    store_tile(oh + ((size_t)b * S_ + sq0) * DM + h * 64, DM, wm, wn, lane, acc, 1.0f);
}

// ---------------- LayerNorm (shuffle reductions, 2 barriers) ----------------
__global__ void ln_kernel(const float* __restrict__ x, float* __restrict__ y,
                          const float* __restrict__ g, const float* __restrict__ bb) {
    int row = blockIdx.x;
    int t = threadIdx.x, lane = t & 31, wid = t >> 5;
    float2 f = *(const float2*)&x[(size_t)row * DM + 2 * t];
    __shared__ float redm[8], redv[8];
    float s = f.x + f.y;
    #pragma unroll
    for (int o = 16; o; o >>= 1) s += __shfl_xor_sync(0xffffffffu, s, o);
    if (lane == 0) redm[wid] = s;
    __syncthreads();
    float mu = 0.f;
    #pragma unroll
    for (int i = 0; i < 8; i++) mu += redm[i];
    mu *= (1.0f / DM);
    float d0 = f.x - mu, d1 = f.y - mu;
    float vv = d0 * d0 + d1 * d1;
    #pragma unroll
    for (int o = 16; o; o >>= 1) vv += __shfl_xor_sync(0xffffffffu, vv, o);
    if (lane == 0) redv[wid] = vv;
    __syncthreads();
    float var = 0.f;
    #pragma unroll
    for (int i = 0; i < 8; i++) var += redv[i];
    float rstd = rsqrtf(var * (1.0f / DM) + 1e-5f);
    float2 gg = *(const float2*)&g[2 * t];
    float2 bv = *(const float2*)&bb[2 * t];
    float2 out;
    out.x = d0 * rstd * gg.x + bv.x;
    out.y = d1 * rstd * gg.y + bv.y;
    *(float2*)&y[(size_t)row * DM + 2 * t] = out;
}

// ---------------- softmax (shuffle reductions, 2 barriers) ----------------
__global__ __launch_bounds__(256) void softmax_kernel(float* __restrict__ attn) {
    size_t row = blockIdx.x;
    float4* p = (float4*)(attn + row * (size_t)S_);
    int tid = threadIdx.x, lane = tid & 31, wid = tid >> 5;
    float4 v0 = p[tid], v1 = p[tid + 256];
    float m = fmaxf(fmaxf(fmaxf(v0.x, v0.y), fmaxf(v0.z, v0.w)),
                    fmaxf(fmaxf(v1.x, v1.y), fmaxf(v1.z, v1.w)));
    __shared__ float redm[8], reds[8];
    #pragma unroll
    for (int o = 16; o; o >>= 1) m = fmaxf(m, __shfl_xor_sync(0xffffffffu, m, o));
    if (lane == 0) redm[wid] = m;
    __syncthreads();
    m = redm[0];
    #pragma unroll
    for (int i = 1; i < 8; i++) m = fmaxf(m, redm[i]);
    v0.x = __expf(v0.x - m); v0.y = __expf(v0.y - m); v0.z = __expf(v0.z - m); v0.w = __expf(v0.w - m);
    v1.x = __expf(v1.x - m); v1.y = __expf(v1.y - m); v1.z = __expf(v1.z - m); v1.w = __expf(v1.w - m);
    float s = v0.x + v0.y + v0.z + v0.w + v1.x + v1.y + v1.z + v1.w;
    #pragma unroll
    for (int o = 16; o; o >>= 1) s += __shfl_xor_sync(0xffffffffu, s, o);
    if (lane == 0) reds[wid] = s;
    __syncthreads();
    s = 0.f;
    #pragma unroll
    for (int i = 0; i < 8; i++) s += reds[i];
    float inv = 1.0f / s;
    v0.x *= inv; v0.y *= inv; v0.z *= inv; v0.w *= inv;
    v1.x *= inv; v1.y *= inv; v1.z *= inv; v1.w *= inv;
    p[tid] = v0;
    p[tid + 256] = v1;
}

extern "C" void kernel_launch(void* const* d_in, const int* in_sizes, int n_in,
                              void* d_out, int out_size) {
    const float* q    = (const float*)d_in[0];
    const float* k    = (const float*)d_in[1];
    const float* v    = (const float*)d_in[2];
    const float* W_Q  = (const float*)d_in[3];
    const float* W_K  = (const float*)d_in[4];
    const float* W_V  = (const float*)d_in[5];
    const float* W_fc = (const float*)d_in[6];
    const float* ln_g = (const float*)d_in[7];
    const float* ln_b = (const float*)d_in[8];

    float* out  = (float*)d_out;                       // [B,S,512]
    float* attn = out + (size_t)B_ * S_ * DM;          // [B,H,S,S]

    float *buf, *qp, *kp, *vp, *oh;
    cudaGetSymbolAddress((void**)&buf, g_buf);
    cudaGetSymbolAddress((void**)&qp,  g_qp);
    cudaGetSymbolAddress((void**)&kp,  g_kp);
    cudaGetSymbolAddress((void**)&vp,  g_vp);
    cudaGetSymbolAddress((void**)&oh,  g_oh);

    const int SMEM    = 48 * 1024;
    const int SMEM_S  = 64 * 1024;
    const int SMEM_AV = 32 * 1024;
    cudaFuncSetAttribute(proj_mma,   cudaFuncAttributeMaxDynamicSharedMemorySize, SMEM);
    cudaFuncSetAttribute(scores_mma, cudaFuncAttributeMaxDynamicSharedMemorySize, SMEM_S);
    cudaFuncSetAttribute(av_mma,     cudaFuncAttributeMaxDynamicSharedMemorySize, SMEM_AV);

    const int ROWS = B_ * S_;                          // 8192
    dim3 proj_grid(DM / 64, ROWS / 128);               // (8, 64)

    // Q path
    ln_kernel<<<ROWS, 256>>>(q, buf, ln_g, ln_b);
    proj_mma<<<proj_grid, 256, SMEM>>>(buf, W_Q, qp);
    // K path
    ln_kernel<<<ROWS, 256>>>(k, buf, ln_g, ln_b);
    proj_mma<<<proj_grid, 256, SMEM>>>(buf, W_K, kp);
    // V path
    ln_kernel<<<ROWS, 256>>>(v, buf, ln_g, ln_b);
    proj_mma<<<proj_grid, 256, SMEM>>>(buf, W_V, vp);

    // Attention
    scores_mma<<<dim3(S_ / 512, S_ / 128, B_ * H_), 256, SMEM_S>>>(qp, kp, attn);
    softmax_kernel<<<B_ * H_ * S_, 256>>>(attn);
    av_mma<<<dim3(S_ / 128, B_ * H_), 256, SMEM_AV>>>(attn, vp, oh);

    // Output LN + fc
    ln_kernel<<<ROWS, 256>>>(oh, buf, ln_g, ln_b);
    proj_mma<<<proj_grid, 256, SMEM>>>(buf, W_fc, out);
}